// round 1
// baseline (speedup 1.0000x reference)
#include <cuda_runtime.h>
#include <cuda_bf16.h>
#include <math.h>

#define N_NODES 100000
#define N_EDGES 600000
#define N_GRAPHS 1024
#define F_IN 32
#define GHC 128
#define NHID 512
#define NOUT 256
#define N_LAYERS 5
#define BN_EPS 1e-5f
#define ZDIM (N_LAYERS * GHC)   // 640

// ---------------- device scratch (no allocations allowed) ----------------
__device__ float  g_hsum[N_NODES * GHC];     // x + agg   (layer0 uses 32-wide)
__device__ float  g_hid [N_NODES * 2 * GHC]; // MLP hidden (256)
__device__ float  g_pre [N_NODES * GHC];     // pre-BN
__device__ float  g_h   [N_NODES * GHC];     // layer output
__device__ int    g_rowptr[N_NODES + 1];
__device__ int    g_deg   [N_NODES];         // also used as cursor
__device__ int    g_csr   [N_EDGES];
__device__ int    g_blocksums[128];
__device__ int    g_blockoffs[128];
__device__ double g_sum[GHC], g_sumsq[GHC];
__device__ float  g_scale[GHC], g_shift[GHC];
__device__ float  g_z  [N_GRAPHS * ZDIM];
__device__ float  g_zh [N_GRAPHS * NHID];
__device__ int    g_cnt[N_GRAPHS];
__device__ int    g_is64;

// ---------------- helpers ----------------
__device__ __forceinline__ int ld_idx(const void* p, long i) {
    if (g_is64) return (int)((const long long*)p)[i];
    return ((const int*)p)[i];
}

__global__ void k_probe(const unsigned int* ei_words) {
    if (threadIdx.x == 0 && blockIdx.x == 0) {
        unsigned int nz = 0;
        for (int i = 0; i < 256; i++) nz |= ei_words[2 * i + 1];
        g_is64 = (nz == 0) ? 1 : 0;
    }
}

__global__ void k_zero_u32(unsigned int* p, int n) {
    int i = blockIdx.x * blockDim.x + threadIdx.x;
    if (i < n) p[i] = 0u;
}

// ---------------- CSR build ----------------
__global__ void k_deg(const void* ei) {
    int e = blockIdx.x * blockDim.x + threadIdx.x;
    if (e < N_EDGES) {
        int dst = ld_idx(ei, (long)N_EDGES + e);
        atomicAdd(&g_deg[dst], 1);
    }
}

__global__ void k_scan1() {
    __shared__ int sh[1024];
    int gid = blockIdx.x * 1024 + threadIdx.x;
    int v = (gid < N_NODES) ? g_deg[gid] : 0;
    sh[threadIdx.x] = v;
    __syncthreads();
    for (int off = 1; off < 1024; off <<= 1) {
        int t = (threadIdx.x >= off) ? sh[threadIdx.x - off] : 0;
        __syncthreads();
        sh[threadIdx.x] += t;
        __syncthreads();
    }
    if (gid < N_NODES) g_rowptr[gid] = sh[threadIdx.x] - v;   // exclusive
    if (threadIdx.x == 1023) g_blocksums[blockIdx.x] = sh[1023];
}

__global__ void k_scan2(int nb) {
    if (threadIdx.x == 0 && blockIdx.x == 0) {
        int run = 0;
        for (int b = 0; b < nb; b++) { g_blockoffs[b] = run; run += g_blocksums[b]; }
    }
}

__global__ void k_scan3() {
    int gid = blockIdx.x * 1024 + threadIdx.x;
    if (gid < N_NODES) {
        int r = g_rowptr[gid] + g_blockoffs[blockIdx.x];
        g_rowptr[gid] = r;
        g_deg[gid] = r;                 // cursor for scatter
    }
    if (gid == 0) g_rowptr[N_NODES] = N_EDGES;
}

__global__ void k_scatter(const void* ei) {
    int e = blockIdx.x * blockDim.x + threadIdx.x;
    if (e < N_EDGES) {
        int src = ld_idx(ei, e);
        int dst = ld_idx(ei, (long)N_EDGES + e);
        int pos = atomicAdd(&g_deg[dst], 1);
        g_csr[pos] = src;
    }
}

__global__ void k_count(const void* batch) {
    int i = blockIdx.x * blockDim.x + threadIdx.x;
    if (i < N_NODES) atomicAdd(&g_cnt[ld_idx(batch, i)], 1);
}

// ---------------- aggregation: h_sum = x + sum_{j->i} x_j ----------------
__global__ void k_agg32(const float* __restrict__ x) {
    int t = blockIdx.x * blockDim.x + threadIdx.x;
    int node = t >> 5, lane = t & 31;
    if (node >= N_NODES) return;
    float acc = x[node * 32 + lane];
    int e0 = g_rowptr[node], e1 = g_rowptr[node + 1];
    for (int e = e0; e < e1; e++) {
        int s = g_csr[e];
        acc += x[s * 32 + lane];
    }
    g_hsum[node * 32 + lane] = acc;
}

__global__ void k_agg128() {
    int t = blockIdx.x * blockDim.x + threadIdx.x;
    int node = t >> 5, lane = t & 31;
    if (node >= N_NODES) return;
    const float4* hin = (const float4*)g_h;
    float4 acc = hin[node * 32 + lane];
    int e0 = g_rowptr[node], e1 = g_rowptr[node + 1];
    for (int e = e0; e < e1; e++) {
        int s = g_csr[e];
        float4 v = hin[s * 32 + lane];
        acc.x += v.x; acc.y += v.y; acc.z += v.z; acc.w += v.w;
    }
    ((float4*)g_hsum)[node * 32 + lane] = acc;
}

// ---------------- SGEMM: C = act(A[M,K] @ B[K,N] + bias) ----------------
// BM=64 BN=64 BK=16, 256 threads, 4x4 per thread. K % 16 == 0, N % 64 == 0.
template<bool RELU>
__global__ void k_sgemm(const float* __restrict__ A, const float* __restrict__ B,
                        const float* __restrict__ bias, float* __restrict__ C,
                        int M, int N, int K) {
    __shared__ float As[16][65];
    __shared__ float Bs[16][68];
    int bm = blockIdx.x * 64, bn = blockIdx.y * 64;
    int tid = threadIdx.x;
    int tr = tid >> 4, tc = tid & 15;   // 16x16 thread grid, 4x4 each

    float acc[4][4];
#pragma unroll
    for (int i = 0; i < 4; i++)
#pragma unroll
        for (int j = 0; j < 4; j++) acc[i][j] = 0.f;

    int ar = tid >> 2, akq = (tid & 3) << 2;     // A: row ar (0..63), k quad
    int bk = tid >> 4, bcq = (tid & 15) << 2;    // B: k row (0..15), col quad

    for (int k0 = 0; k0 < K; k0 += 16) {
        // load A 64x16 (transposed to As[k][m])
        float4 av;
        if (bm + ar < M) av = *(const float4*)&A[(long)(bm + ar) * K + k0 + akq];
        else             av = make_float4(0.f, 0.f, 0.f, 0.f);
        As[akq + 0][ar] = av.x;
        As[akq + 1][ar] = av.y;
        As[akq + 2][ar] = av.z;
        As[akq + 3][ar] = av.w;
        // load B 16x64
        float4 bv = *(const float4*)&B[(long)(k0 + bk) * N + bn + bcq];
        *(float4*)&Bs[bk][bcq] = bv;
        __syncthreads();
#pragma unroll
        for (int k = 0; k < 16; k++) {
            float a0 = As[k][tr * 4 + 0];
            float a1 = As[k][tr * 4 + 1];
            float a2 = As[k][tr * 4 + 2];
            float a3 = As[k][tr * 4 + 3];
            float4 b = *(const float4*)&Bs[k][tc * 4];
            acc[0][0] += a0 * b.x; acc[0][1] += a0 * b.y; acc[0][2] += a0 * b.z; acc[0][3] += a0 * b.w;
            acc[1][0] += a1 * b.x; acc[1][1] += a1 * b.y; acc[1][2] += a1 * b.z; acc[1][3] += a1 * b.w;
            acc[2][0] += a2 * b.x; acc[2][1] += a2 * b.y; acc[2][2] += a2 * b.z; acc[2][3] += a2 * b.w;
            acc[3][0] += a3 * b.x; acc[3][1] += a3 * b.y; acc[3][2] += a3 * b.z; acc[3][3] += a3 * b.w;
        }
        __syncthreads();
    }

    float bb[4];
#pragma unroll
    for (int j = 0; j < 4; j++) bb[j] = bias[bn + tc * 4 + j];
#pragma unroll
    for (int i = 0; i < 4; i++) {
        int row = bm + tr * 4 + i;
        if (row < M) {
#pragma unroll
            for (int j = 0; j < 4; j++) {
                float v = acc[i][j] + bb[j];
                if (RELU) v = fmaxf(v, 0.f);
                C[(long)row * N + bn + tc * 4 + j] = v;
            }
        }
    }
}

// ---------------- BatchNorm ----------------
__global__ void k_bn_reduce() {
    int c = threadIdx.x;                         // 128 channels
    int rows_per = (N_NODES + gridDim.x - 1) / gridDim.x;
    int r0 = blockIdx.x * rows_per;
    int r1 = min(r0 + rows_per, N_NODES);
    float s = 0.f, s2 = 0.f;
    for (int r = r0; r < r1; r++) {
        float v = g_pre[(long)r * GHC + c];
        s += v; s2 += v * v;
    }
    atomicAdd(&g_sum[c], (double)s);
    atomicAdd(&g_sumsq[c], (double)s2);
}

__global__ void k_bn_final(const float* __restrict__ gamma, const float* __restrict__ beta) {
    int c = threadIdx.x;
    double mu = g_sum[c] / (double)N_NODES;
    double var = g_sumsq[c] / (double)N_NODES - mu * mu;
    double inv = 1.0 / sqrt(var + (double)BN_EPS);
    double sc = (double)gamma[c] * inv;
    g_scale[c] = (float)sc;
    g_shift[c] = (float)((double)beta[c] - mu * sc);
}

// BN apply + relu + store next-layer input + pooled accumulation
__global__ void k_bn_apply(const void* batch, int lofs) {
    long idx = (long)blockIdx.x * blockDim.x + threadIdx.x;
    if (idx >= (long)N_NODES * GHC) return;
    int i = (int)(idx >> 7), c = (int)(idx & 127);
    float v = g_pre[idx] * g_scale[c] + g_shift[c];
    v = fmaxf(v, 0.f);
    g_h[idx] = v;
    int gph = ld_idx(batch, i);
    atomicAdd(&g_z[(long)gph * ZDIM + lofs + c], v);
}

__global__ void k_div() {
    int idx = blockIdx.x * blockDim.x + threadIdx.x;
    if (idx >= N_GRAPHS * ZDIM) return;
    int gph = idx / ZDIM;
    float cnt = (float)max(g_cnt[gph], 1);
    g_z[idx] *= (1.f / cnt);
}

// ---------------- launch ----------------
extern "C" void kernel_launch(void* const* d_in, const int* in_sizes, int n_in,
                              void* d_out, int out_size) {
    const float* x      = (const float*)d_in[0];
    const void*  ei     = d_in[1];
    const void*  batch  = d_in[2];
    const float* W1_0   = (const float*)d_in[3];
    const float* b1_0   = (const float*)d_in[4];
    const float* W2_0   = (const float*)d_in[5];
    const float* b2_0   = (const float*)d_in[6];
    const float* W1s    = (const float*)d_in[7];
    const float* b1s    = (const float*)d_in[8];
    const float* W2s    = (const float*)d_in[9];
    const float* b2s    = (const float*)d_in[10];
    const float* gamma  = (const float*)d_in[11];
    const float* beta   = (const float*)d_in[12];
    const float* Wm1    = (const float*)d_in[13];
    const float* bm1    = (const float*)d_in[14];
    const float* Wm2    = (const float*)d_in[15];
    const float* bm2    = (const float*)d_in[16];
    float* out = (float*)d_out;

    void *p_hsum, *p_hid, *p_pre, *p_z, *p_zh, *p_deg, *p_cnt, *p_sum;
    cudaGetSymbolAddress(&p_hsum, g_hsum);
    cudaGetSymbolAddress(&p_hid,  g_hid);
    cudaGetSymbolAddress(&p_pre,  g_pre);
    cudaGetSymbolAddress(&p_z,    g_z);
    cudaGetSymbolAddress(&p_zh,   g_zh);
    cudaGetSymbolAddress(&p_deg,  g_deg);
    cudaGetSymbolAddress(&p_cnt,  g_cnt);
    cudaGetSymbolAddress(&p_sum,  g_sum);

    const int NB = (N_NODES + 1023) / 1024;   // 98

    // dtype probe + CSR build + counts + pooled zero
    k_probe<<<1, 32>>>((const unsigned int*)ei);
    k_zero_u32<<<(N_NODES + 255) / 256, 256>>>((unsigned int*)p_deg, N_NODES);
    k_zero_u32<<<(N_GRAPHS + 255) / 256, 256>>>((unsigned int*)p_cnt, N_GRAPHS);
    k_zero_u32<<<(N_GRAPHS * ZDIM + 255) / 256, 256>>>((unsigned int*)p_z, N_GRAPHS * ZDIM);
    k_deg<<<(N_EDGES + 255) / 256, 256>>>(ei);
    k_count<<<(N_NODES + 255) / 256, 256>>>(batch);
    k_scan1<<<NB, 1024>>>();
    k_scan2<<<1, 1>>>(NB);
    k_scan3<<<NB, 1024>>>();
    k_scatter<<<(N_EDGES + 255) / 256, 256>>>(ei);

    dim3 gA((N_NODES * 32 + 255) / 256);      // warp per node

    for (int l = 0; l < N_LAYERS; l++) {
        int K1;
        const float *W1, *B1, *W2, *B2;
        if (l == 0) {
            K1 = F_IN; W1 = W1_0; B1 = b1_0; W2 = W2_0; B2 = b2_0;
            k_agg32<<<gA, 256>>>(x);
        } else {
            K1 = GHC;
            W1 = W1s + (long)(l - 1) * GHC * 2 * GHC;
            B1 = b1s + (long)(l - 1) * 2 * GHC;
            W2 = W2s + (long)(l - 1) * 2 * GHC * GHC;
            B2 = b2s + (long)(l - 1) * GHC;
            k_agg128<<<gA, 256>>>();
        }
        // MLP
        {
            dim3 g1((N_NODES + 63) / 64, (2 * GHC) / 64);
            k_sgemm<true><<<g1, 256>>>((const float*)p_hsum, W1, B1, (float*)p_hid,
                                       N_NODES, 2 * GHC, K1);
            dim3 g2((N_NODES + 63) / 64, GHC / 64);
            k_sgemm<false><<<g2, 256>>>((const float*)p_hid, W2, B2, (float*)p_pre,
                                        N_NODES, GHC, 2 * GHC);
        }
        // BN (+relu) + pool accumulate
        k_zero_u32<<<1, 512>>>((unsigned int*)p_sum, 4 * GHC);  // g_sum+g_sumsq (contiguous doubles)
        k_bn_reduce<<<256, GHC>>>();
        k_bn_final<<<1, GHC>>>(gamma + l * GHC, beta + l * GHC);
        long napply = (long)N_NODES * GHC;
        k_bn_apply<<<(unsigned)((napply + 255) / 256), 256>>>(batch, l * GHC);
    }

    // mean pool divide + final MLP
    k_div<<<(N_GRAPHS * ZDIM + 255) / 256, 256>>>();
    {
        dim3 g1(N_GRAPHS / 64, NHID / 64);
        k_sgemm<true><<<g1, 256>>>((const float*)p_z, Wm1, bm1, (float*)p_zh,
                                   N_GRAPHS, NHID, ZDIM);
        dim3 g2(N_GRAPHS / 64, NOUT / 64);
        k_sgemm<false><<<g2, 256>>>((const float*)p_zh, Wm2, bm2, out,
                                    N_GRAPHS, NOUT, NHID);
    }
}

// round 2
// speedup vs baseline: 1.8460x; 1.8460x over previous
#include <cuda_runtime.h>
#include <cuda_bf16.h>
#include <math.h>
#include <stdint.h>

#define N_NODES 100000
#define N_EDGES 600000
#define N_GRAPHS 1024
#define F_IN 32
#define GHC 128
#define NHID 512
#define NOUT 256
#define N_LAYERS 5
#define BN_EPS 1e-5f
#define ZDIM (N_LAYERS * GHC)   // 640

// ---------------- device scratch (no allocations allowed) ----------------
__device__ float  g_hsum[N_NODES * GHC];     // x + agg   (layer0 uses 32-wide)
__device__ float  g_hid [N_NODES * 2 * GHC]; // MLP hidden (256)
__device__ float  g_pre [N_NODES * GHC];     // pre-BN
__device__ float  g_h   [N_NODES * GHC];     // layer output
__device__ int    g_rowptr[N_NODES + 1];
__device__ int    g_deg   [N_NODES];         // also used as cursor
__device__ int    g_csr   [N_EDGES];
__device__ int    g_blocksums[128];
__device__ int    g_blockoffs[128];
__device__ double g_sum[GHC], g_sumsq[GHC];
__device__ float  g_scale[GHC], g_shift[GHC];
__device__ float  g_z  [N_GRAPHS * ZDIM];
__device__ float  g_zh [N_GRAPHS * NHID];
__device__ int    g_cnt[N_GRAPHS];
__device__ int    g_is64;

// ---------------- helpers ----------------
__device__ __forceinline__ int ld_idx(const void* p, long i) {
    if (g_is64) return (int)((const long long*)p)[i];
    return ((const int*)p)[i];
}

__device__ __forceinline__ uint32_t f2tf(float f) {
    uint32_t u;
    asm("cvt.rna.tf32.f32 %0, %1;" : "=r"(u) : "f"(f));
    return u;
}

__global__ void k_probe(const unsigned int* ei_words) {
    if (threadIdx.x == 0 && blockIdx.x == 0) {
        unsigned int nz = 0;
        for (int i = 0; i < 256; i++) nz |= ei_words[2 * i + 1];
        g_is64 = (nz == 0) ? 1 : 0;
    }
}

__global__ void k_zero_u32(unsigned int* p, int n) {
    int i = blockIdx.x * blockDim.x + threadIdx.x;
    if (i < n) p[i] = 0u;
}

// ---------------- CSR build ----------------
__global__ void k_deg(const void* ei) {
    int e = blockIdx.x * blockDim.x + threadIdx.x;
    if (e < N_EDGES) {
        int dst = ld_idx(ei, (long)N_EDGES + e);
        atomicAdd(&g_deg[dst], 1);
    }
}

__global__ void k_scan1() {
    __shared__ int sh[1024];
    int gid = blockIdx.x * 1024 + threadIdx.x;
    int v = (gid < N_NODES) ? g_deg[gid] : 0;
    sh[threadIdx.x] = v;
    __syncthreads();
    for (int off = 1; off < 1024; off <<= 1) {
        int t = (threadIdx.x >= off) ? sh[threadIdx.x - off] : 0;
        __syncthreads();
        sh[threadIdx.x] += t;
        __syncthreads();
    }
    if (gid < N_NODES) g_rowptr[gid] = sh[threadIdx.x] - v;   // exclusive
    if (threadIdx.x == 1023) g_blocksums[blockIdx.x] = sh[1023];
}

__global__ void k_scan2(int nb) {
    if (threadIdx.x == 0 && blockIdx.x == 0) {
        int run = 0;
        for (int b = 0; b < nb; b++) { g_blockoffs[b] = run; run += g_blocksums[b]; }
    }
}

__global__ void k_scan3() {
    int gid = blockIdx.x * 1024 + threadIdx.x;
    if (gid < N_NODES) {
        int r = g_rowptr[gid] + g_blockoffs[blockIdx.x];
        g_rowptr[gid] = r;
        g_deg[gid] = r;                 // cursor for scatter
    }
    if (gid == 0) g_rowptr[N_NODES] = N_EDGES;
}

__global__ void k_scatter(const void* ei) {
    int e = blockIdx.x * blockDim.x + threadIdx.x;
    if (e < N_EDGES) {
        int src = ld_idx(ei, e);
        int dst = ld_idx(ei, (long)N_EDGES + e);
        int pos = atomicAdd(&g_deg[dst], 1);
        g_csr[pos] = src;
    }
}

__global__ void k_count(const void* batch) {
    int i = blockIdx.x * blockDim.x + threadIdx.x;
    if (i < N_NODES) atomicAdd(&g_cnt[ld_idx(batch, i)], 1);
}

// ---------------- aggregation: h_sum = x + sum_{j->i} x_j ----------------
__global__ void k_agg32(const float* __restrict__ x) {
    int t = blockIdx.x * blockDim.x + threadIdx.x;
    int node = t >> 5, lane = t & 31;
    if (node >= N_NODES) return;
    float acc = x[node * 32 + lane];
    int e0 = g_rowptr[node], e1 = g_rowptr[node + 1];
    for (int e = e0; e < e1; e++) {
        int s = g_csr[e];
        acc += x[s * 32 + lane];
    }
    g_hsum[node * 32 + lane] = acc;
}

__global__ void k_agg128() {
    int t = blockIdx.x * blockDim.x + threadIdx.x;
    int node = t >> 5, lane = t & 31;
    if (node >= N_NODES) return;
    const float4* hin = (const float4*)g_h;
    float4 acc = hin[node * 32 + lane];
    int e0 = g_rowptr[node], e1 = g_rowptr[node + 1];
    for (int e = e0; e < e1; e++) {
        int s = g_csr[e];
        float4 v = hin[s * 32 + lane];
        acc.x += v.x; acc.y += v.y; acc.z += v.z; acc.w += v.w;
    }
    ((float4*)g_hsum)[node * 32 + lane] = acc;
}

// ---------------- TF32 tensor-core GEMM ----------------
// C[M,N] = act(A[M,K] @ B[K,N] + bias),  A,B,C row-major fp32 (TF32 compute).
// Block tile 128x128x32, 256 threads (8 warps as 4m x 2n, warp tile 32x64).
// Requires K%32==0, N%128==0. M guarded.
#define AS_LD 36   // padded stride (floats): banks (4g+tg) all distinct
#define BS_LD 136  // padded stride (floats): banks (8tg+g) all distinct

template<bool RELU>
__global__ void __launch_bounds__(256)
k_mma(const float* __restrict__ A, const float* __restrict__ B,
      const float* __restrict__ bias, float* __restrict__ C,
      int M, int N, int K) {
    __shared__ uint32_t As[128 * AS_LD];
    __shared__ uint32_t Bs[32 * BS_LD];

    const int tid  = threadIdx.x;
    const int bm   = blockIdx.x * 128, bn = blockIdx.y * 128;
    const int warp = tid >> 5, lane = tid & 31;
    const int wm   = (warp & 3) * 32;        // warp row offset in tile
    const int wn   = (warp >> 2) * 64;       // warp col offset in tile
    const int gr   = lane >> 2, tg = lane & 3;

    float c[2][8][4];
#pragma unroll
    for (int mi = 0; mi < 2; mi++)
#pragma unroll
        for (int ni = 0; ni < 8; ni++)
#pragma unroll
            for (int j = 0; j < 4; j++) c[mi][ni][j] = 0.f;

    float4 ra[4], rb[4];

    // prefetch k0 = 0
    {
        int k0 = 0;
#pragma unroll
        for (int it = 0; it < 4; it++) {
            int idx = it * 256 + tid;
            int row = idx >> 3, cq = (idx & 7) << 2;       // A tile 128x32
            if (bm + row < M) ra[it] = *(const float4*)&A[(long)(bm + row) * K + k0 + cq];
            else              ra[it] = make_float4(0.f, 0.f, 0.f, 0.f);
            int rowB = idx >> 5, cqB = (idx & 31) << 2;    // B tile 32x128
            rb[it] = *(const float4*)&B[(long)(k0 + rowB) * N + bn + cqB];
        }
    }

    for (int k0 = 0; k0 < K; k0 += 32) {
        // regs -> smem (with tf32 rounding)
#pragma unroll
        for (int it = 0; it < 4; it++) {
            int idx = it * 256 + tid;
            int row = idx >> 3, cq = (idx & 7) << 2;
            uint4 ua = make_uint4(f2tf(ra[it].x), f2tf(ra[it].y), f2tf(ra[it].z), f2tf(ra[it].w));
            *(uint4*)&As[row * AS_LD + cq] = ua;
            int rowB = idx >> 5, cqB = (idx & 31) << 2;
            uint4 ub = make_uint4(f2tf(rb[it].x), f2tf(rb[it].y), f2tf(rb[it].z), f2tf(rb[it].w));
            *(uint4*)&Bs[rowB * BS_LD + cqB] = ub;
        }
        __syncthreads();

        // prefetch next tile while computing
        if (k0 + 32 < K) {
            int kn = k0 + 32;
#pragma unroll
            for (int it = 0; it < 4; it++) {
                int idx = it * 256 + tid;
                int row = idx >> 3, cq = (idx & 7) << 2;
                if (bm + row < M) ra[it] = *(const float4*)&A[(long)(bm + row) * K + kn + cq];
                else              ra[it] = make_float4(0.f, 0.f, 0.f, 0.f);
                int rowB = idx >> 5, cqB = (idx & 31) << 2;
                rb[it] = *(const float4*)&B[(long)(kn + rowB) * N + bn + cqB];
            }
        }

#pragma unroll
        for (int kk = 0; kk < 32; kk += 8) {
            uint32_t a[2][4];
#pragma unroll
            for (int mi = 0; mi < 2; mi++) {
                int r0 = wm + mi * 16 + gr;
                a[mi][0] = As[r0 * AS_LD + kk + tg];
                a[mi][1] = As[(r0 + 8) * AS_LD + kk + tg];
                a[mi][2] = As[r0 * AS_LD + kk + tg + 4];
                a[mi][3] = As[(r0 + 8) * AS_LD + kk + tg + 4];
            }
            uint32_t b[8][2];
#pragma unroll
            for (int ni = 0; ni < 8; ni++) {
                int col = wn + ni * 8 + gr;
                b[ni][0] = Bs[(kk + tg) * BS_LD + col];
                b[ni][1] = Bs[(kk + tg + 4) * BS_LD + col];
            }
#pragma unroll
            for (int mi = 0; mi < 2; mi++)
#pragma unroll
                for (int ni = 0; ni < 8; ni++) {
                    asm volatile(
                        "mma.sync.aligned.m16n8k8.row.col.f32.tf32.tf32.f32 "
                        "{%0,%1,%2,%3},{%4,%5,%6,%7},{%8,%9},{%0,%1,%2,%3};"
                        : "+f"(c[mi][ni][0]), "+f"(c[mi][ni][1]),
                          "+f"(c[mi][ni][2]), "+f"(c[mi][ni][3])
                        : "r"(a[mi][0]), "r"(a[mi][1]), "r"(a[mi][2]), "r"(a[mi][3]),
                          "r"(b[ni][0]), "r"(b[ni][1]));
                }
        }
        __syncthreads();
    }

    // epilogue: bias + optional relu
#pragma unroll
    for (int mi = 0; mi < 2; mi++) {
        int r0 = bm + wm + mi * 16 + gr;
        int r1 = r0 + 8;
#pragma unroll
        for (int ni = 0; ni < 8; ni++) {
            int col = bn + wn + ni * 8 + tg * 2;
            float b0 = bias[col], b1 = bias[col + 1];
            float v0 = c[mi][ni][0] + b0, v1 = c[mi][ni][1] + b1;
            float v2 = c[mi][ni][2] + b0, v3 = c[mi][ni][3] + b1;
            if (RELU) {
                v0 = fmaxf(v0, 0.f); v1 = fmaxf(v1, 0.f);
                v2 = fmaxf(v2, 0.f); v3 = fmaxf(v3, 0.f);
            }
            if (r0 < M) { float2 p = make_float2(v0, v1); *(float2*)&C[(long)r0 * N + col] = p; }
            if (r1 < M) { float2 p = make_float2(v2, v3); *(float2*)&C[(long)r1 * N + col] = p; }
        }
    }
}

// ---------------- BatchNorm ----------------
__global__ void k_bn_reduce() {
    int c = threadIdx.x;                         // 128 channels
    int rows_per = (N_NODES + gridDim.x - 1) / gridDim.x;
    int r0 = blockIdx.x * rows_per;
    int r1 = min(r0 + rows_per, N_NODES);
    float s = 0.f, s2 = 0.f;
    for (int r = r0; r < r1; r++) {
        float v = g_pre[(long)r * GHC + c];
        s += v; s2 += v * v;
    }
    atomicAdd(&g_sum[c], (double)s);
    atomicAdd(&g_sumsq[c], (double)s2);
}

__global__ void k_bn_final(const float* __restrict__ gamma, const float* __restrict__ beta) {
    int c = threadIdx.x;
    double mu = g_sum[c] / (double)N_NODES;
    double var = g_sumsq[c] / (double)N_NODES - mu * mu;
    double inv = 1.0 / sqrt(var + (double)BN_EPS);
    double sc = (double)gamma[c] * inv;
    g_scale[c] = (float)sc;
    g_shift[c] = (float)((double)beta[c] - mu * sc);
}

// BN apply + relu + store next-layer input + pooled accumulation
__global__ void k_bn_apply(const void* batch, int lofs) {
    long idx = (long)blockIdx.x * blockDim.x + threadIdx.x;
    if (idx >= (long)N_NODES * GHC) return;
    int i = (int)(idx >> 7), c = (int)(idx & 127);
    float v = g_pre[idx] * g_scale[c] + g_shift[c];
    v = fmaxf(v, 0.f);
    g_h[idx] = v;
    int gph = ld_idx(batch, i);
    atomicAdd(&g_z[(long)gph * ZDIM + lofs + c], v);
}

__global__ void k_div() {
    int idx = blockIdx.x * blockDim.x + threadIdx.x;
    if (idx >= N_GRAPHS * ZDIM) return;
    int gph = idx / ZDIM;
    float cnt = (float)max(g_cnt[gph], 1);
    g_z[idx] *= (1.f / cnt);
}

// ---------------- launch ----------------
extern "C" void kernel_launch(void* const* d_in, const int* in_sizes, int n_in,
                              void* d_out, int out_size) {
    const float* x      = (const float*)d_in[0];
    const void*  ei     = d_in[1];
    const void*  batch  = d_in[2];
    const float* W1_0   = (const float*)d_in[3];
    const float* b1_0   = (const float*)d_in[4];
    const float* W2_0   = (const float*)d_in[5];
    const float* b2_0   = (const float*)d_in[6];
    const float* W1s    = (const float*)d_in[7];
    const float* b1s    = (const float*)d_in[8];
    const float* W2s    = (const float*)d_in[9];
    const float* b2s    = (const float*)d_in[10];
    const float* gamma  = (const float*)d_in[11];
    const float* beta   = (const float*)d_in[12];
    const float* Wm1    = (const float*)d_in[13];
    const float* bm1    = (const float*)d_in[14];
    const float* Wm2    = (const float*)d_in[15];
    const float* bm2    = (const float*)d_in[16];
    float* out = (float*)d_out;

    void *p_hsum, *p_hid, *p_pre, *p_z, *p_zh, *p_deg, *p_cnt, *p_sum;
    cudaGetSymbolAddress(&p_hsum, g_hsum);
    cudaGetSymbolAddress(&p_hid,  g_hid);
    cudaGetSymbolAddress(&p_pre,  g_pre);
    cudaGetSymbolAddress(&p_z,    g_z);
    cudaGetSymbolAddress(&p_zh,   g_zh);
    cudaGetSymbolAddress(&p_deg,  g_deg);
    cudaGetSymbolAddress(&p_cnt,  g_cnt);
    cudaGetSymbolAddress(&p_sum,  g_sum);

    const int NB = (N_NODES + 1023) / 1024;   // 98

    // dtype probe + CSR build + counts + pooled zero
    k_probe<<<1, 32>>>((const unsigned int*)ei);
    k_zero_u32<<<(N_NODES + 255) / 256, 256>>>((unsigned int*)p_deg, N_NODES);
    k_zero_u32<<<(N_GRAPHS + 255) / 256, 256>>>((unsigned int*)p_cnt, N_GRAPHS);
    k_zero_u32<<<(N_GRAPHS * ZDIM + 255) / 256, 256>>>((unsigned int*)p_z, N_GRAPHS * ZDIM);
    k_deg<<<(N_EDGES + 255) / 256, 256>>>(ei);
    k_count<<<(N_NODES + 255) / 256, 256>>>(batch);
    k_scan1<<<NB, 1024>>>();
    k_scan2<<<1, 1>>>(NB);
    k_scan3<<<NB, 1024>>>();
    k_scatter<<<(N_EDGES + 255) / 256, 256>>>(ei);

    dim3 gA((N_NODES * 32 + 255) / 256);      // warp per node

    const int MB = (N_NODES + 127) / 128;     // 782 blocks in M

    for (int l = 0; l < N_LAYERS; l++) {
        int K1;
        const float *W1, *B1, *W2, *B2;
        if (l == 0) {
            K1 = F_IN; W1 = W1_0; B1 = b1_0; W2 = W2_0; B2 = b2_0;
            k_agg32<<<gA, 256>>>(x);
        } else {
            K1 = GHC;
            W1 = W1s + (long)(l - 1) * GHC * 2 * GHC;
            B1 = b1s + (long)(l - 1) * 2 * GHC;
            W2 = W2s + (long)(l - 1) * 2 * GHC * GHC;
            B2 = b2s + (long)(l - 1) * GHC;
            k_agg128<<<gA, 256>>>();
        }
        // MLP (TF32 tensor cores)
        {
            dim3 g1(MB, (2 * GHC) / 128);
            k_mma<true><<<g1, 256>>>((const float*)p_hsum, W1, B1, (float*)p_hid,
                                     N_NODES, 2 * GHC, K1);
            dim3 g2(MB, GHC / 128);
            k_mma<false><<<g2, 256>>>((const float*)p_hid, W2, B2, (float*)p_pre,
                                      N_NODES, GHC, 2 * GHC);
        }
        // BN (+relu) + pool accumulate
        k_zero_u32<<<1, 512>>>((unsigned int*)p_sum, 4 * GHC);  // g_sum+g_sumsq (contiguous doubles)
        k_bn_reduce<<<256, GHC>>>();
        k_bn_final<<<1, GHC>>>(gamma + l * GHC, beta + l * GHC);
        long napply = (long)N_NODES * GHC;
        k_bn_apply<<<(unsigned)((napply + 255) / 256), 256>>>(batch, l * GHC);
    }

    // mean pool divide + final MLP
    k_div<<<(N_GRAPHS * ZDIM + 255) / 256, 256>>>();
    {
        dim3 g1((N_GRAPHS + 127) / 128, NHID / 128);
        k_mma<true><<<g1, 256>>>((const float*)p_z, Wm1, bm1, (float*)p_zh,
                                 N_GRAPHS, NHID, ZDIM);
        dim3 g2((N_GRAPHS + 127) / 128, NOUT / 128);
        k_mma<false><<<g2, 256>>>((const float*)p_zh, Wm2, bm2, out,
                                  N_GRAPHS, NOUT, NHID);
    }
}

// round 3
// speedup vs baseline: 1.9639x; 1.0639x over previous
#include <cuda_runtime.h>
#include <cuda_bf16.h>
#include <math.h>
#include <stdint.h>

#define N_NODES 100000
#define N_EDGES 600000
#define N_GRAPHS 1024
#define F_IN 32
#define GHC 128
#define NHID 512
#define NOUT 256
#define N_LAYERS 5
#define BN_EPS 1e-5f
#define ZDIM (N_LAYERS * GHC)   // 640

// ---------------- device scratch (no allocations allowed) ----------------
__device__ float  g_hsum[N_NODES * GHC];     // x + agg   (layer0 uses 32-wide)
__device__ float  g_hid [N_NODES * 2 * GHC]; // MLP hidden (256)
__device__ float  g_pre [N_NODES * GHC];     // pre-BN
__device__ float  g_h   [N_NODES * GHC];     // layer output
__device__ int    g_rowptr[N_NODES + 1];
__device__ int    g_deg   [N_NODES];         // also used as cursor
__device__ int    g_csr   [N_EDGES];
__device__ int    g_blocksums[128];
__device__ int    g_blockoffs[128];
__device__ double g_sum[GHC], g_sumsq[GHC];
__device__ float  g_scale[GHC], g_shift[GHC];
__device__ float  g_z  [N_GRAPHS * ZDIM];
__device__ float  g_zh [N_GRAPHS * NHID];
__device__ int    g_gstart[N_GRAPHS + 1];
__device__ int    g_is64;

// ---------------- helpers ----------------
__device__ __forceinline__ int ld_idx(const void* p, long i) {
    if (g_is64) return (int)((const long long*)p)[i];
    return ((const int*)p)[i];
}

__device__ __forceinline__ uint32_t f2tf(float f) {
    uint32_t u;
    asm("cvt.rna.tf32.f32 %0, %1;" : "=r"(u) : "f"(f));
    return u;
}

__global__ void k_probe(const unsigned int* ei_words) {
    if (threadIdx.x == 0 && blockIdx.x == 0) {
        unsigned int nz = 0;
        for (int i = 0; i < 256; i++) nz |= ei_words[2 * i + 1];
        g_is64 = (nz == 0) ? 1 : 0;
    }
}

__global__ void k_zero_u32(unsigned int* p, int n) {
    int i = blockIdx.x * blockDim.x + threadIdx.x;
    if (i < n) p[i] = 0u;
}

// ---------------- CSR build ----------------
__global__ void k_deg(const void* ei) {
    int e = blockIdx.x * blockDim.x + threadIdx.x;
    if (e < N_EDGES) {
        int dst = ld_idx(ei, (long)N_EDGES + e);
        atomicAdd(&g_deg[dst], 1);
    }
}

__global__ void k_scan1() {
    __shared__ int sh[1024];
    int gid = blockIdx.x * 1024 + threadIdx.x;
    int v = (gid < N_NODES) ? g_deg[gid] : 0;
    sh[threadIdx.x] = v;
    __syncthreads();
    for (int off = 1; off < 1024; off <<= 1) {
        int t = (threadIdx.x >= off) ? sh[threadIdx.x - off] : 0;
        __syncthreads();
        sh[threadIdx.x] += t;
        __syncthreads();
    }
    if (gid < N_NODES) g_rowptr[gid] = sh[threadIdx.x] - v;   // exclusive
    if (threadIdx.x == 1023) g_blocksums[blockIdx.x] = sh[1023];
}

__global__ void k_scan2(int nb) {
    if (threadIdx.x == 0 && blockIdx.x == 0) {
        int run = 0;
        for (int b = 0; b < nb; b++) { g_blockoffs[b] = run; run += g_blocksums[b]; }
    }
}

__global__ void k_scan3() {
    int gid = blockIdx.x * 1024 + threadIdx.x;
    if (gid < N_NODES) {
        int r = g_rowptr[gid] + g_blockoffs[blockIdx.x];
        g_rowptr[gid] = r;
        g_deg[gid] = r;                 // cursor for scatter
    }
    if (gid == 0) g_rowptr[N_NODES] = N_EDGES;
}

__global__ void k_scatter(const void* ei) {
    int e = blockIdx.x * blockDim.x + threadIdx.x;
    if (e < N_EDGES) {
        int src = ld_idx(ei, e);
        int dst = ld_idx(ei, (long)N_EDGES + e);
        int pos = atomicAdd(&g_deg[dst], 1);
        g_csr[pos] = src;
    }
}

// graph segment starts: lower_bound over sorted batch
__global__ void k_gstart(const void* batch) {
    int g = blockIdx.x * blockDim.x + threadIdx.x;
    if (g > N_GRAPHS) return;
    int lo = 0, hi = N_NODES;
    while (lo < hi) {
        int mid = (lo + hi) >> 1;
        if (ld_idx(batch, mid) < g) lo = mid + 1; else hi = mid;
    }
    g_gstart[g] = lo;
}

// ---------------- aggregation: h_sum = x + sum_{j->i} x_j ----------------
__global__ void k_agg32(const float* __restrict__ x) {
    int t = blockIdx.x * blockDim.x + threadIdx.x;
    int node = t >> 5, lane = t & 31;
    if (node >= N_NODES) return;
    float acc = x[node * 32 + lane];
    int e0 = g_rowptr[node], e1 = g_rowptr[node + 1];
    for (int e = e0; e < e1; e++) {
        int s = g_csr[e];
        acc += x[s * 32 + lane];
    }
    g_hsum[node * 32 + lane] = acc;
}

__global__ void k_agg128() {
    int t = blockIdx.x * blockDim.x + threadIdx.x;
    int node = t >> 5, lane = t & 31;
    if (node >= N_NODES) return;
    const float4* hin = (const float4*)g_h;
    float4 acc = hin[node * 32 + lane];
    int e0 = g_rowptr[node], e1 = g_rowptr[node + 1];
    for (int e = e0; e < e1; e++) {
        int s = g_csr[e];
        float4 v = hin[s * 32 + lane];
        acc.x += v.x; acc.y += v.y; acc.z += v.z; acc.w += v.w;
    }
    ((float4*)g_hsum)[node * 32 + lane] = acc;
}

// ---------------- TF32 tensor-core GEMM ----------------
// C[M,N] = act(A[M,K] @ B[K,N] + bias),  A,B,C row-major fp32 (TF32 compute).
// Block tile 128x128x32, 256 threads (8 warps as 4m x 2n, warp tile 32x64).
// Requires K%32==0, N%128==0. M guarded.
#define AS_LD 36
#define BS_LD 136

template<bool RELU>
__global__ void __launch_bounds__(256)
k_mma(const float* __restrict__ A, const float* __restrict__ B,
      const float* __restrict__ bias, float* __restrict__ C,
      int M, int N, int K) {
    __shared__ uint32_t As[128 * AS_LD];
    __shared__ uint32_t Bs[32 * BS_LD];

    const int tid  = threadIdx.x;
    const int bm   = blockIdx.x * 128, bn = blockIdx.y * 128;
    const int warp = tid >> 5, lane = tid & 31;
    const int wm   = (warp & 3) * 32;        // warp row offset in tile
    const int wn   = (warp >> 2) * 64;       // warp col offset in tile
    const int gr   = lane >> 2, tg = lane & 3;

    float c[2][8][4];
#pragma unroll
    for (int mi = 0; mi < 2; mi++)
#pragma unroll
        for (int ni = 0; ni < 8; ni++)
#pragma unroll
            for (int j = 0; j < 4; j++) c[mi][ni][j] = 0.f;

    float4 ra[4], rb[4];

    // prefetch k0 = 0
    {
        int k0 = 0;
#pragma unroll
        for (int it = 0; it < 4; it++) {
            int idx = it * 256 + tid;
            int row = idx >> 3, cq = (idx & 7) << 2;       // A tile 128x32
            if (bm + row < M) ra[it] = *(const float4*)&A[(long)(bm + row) * K + k0 + cq];
            else              ra[it] = make_float4(0.f, 0.f, 0.f, 0.f);
            int rowB = idx >> 5, cqB = (idx & 31) << 2;    // B tile 32x128
            rb[it] = *(const float4*)&B[(long)(k0 + rowB) * N + bn + cqB];
        }
    }

    for (int k0 = 0; k0 < K; k0 += 32) {
        // regs -> smem (with tf32 rounding)
#pragma unroll
        for (int it = 0; it < 4; it++) {
            int idx = it * 256 + tid;
            int row = idx >> 3, cq = (idx & 7) << 2;
            uint4 ua = make_uint4(f2tf(ra[it].x), f2tf(ra[it].y), f2tf(ra[it].z), f2tf(ra[it].w));
            *(uint4*)&As[row * AS_LD + cq] = ua;
            int rowB = idx >> 5, cqB = (idx & 31) << 2;
            uint4 ub = make_uint4(f2tf(rb[it].x), f2tf(rb[it].y), f2tf(rb[it].z), f2tf(rb[it].w));
            *(uint4*)&Bs[rowB * BS_LD + cqB] = ub;
        }
        __syncthreads();

        // prefetch next tile while computing
        if (k0 + 32 < K) {
            int kn = k0 + 32;
#pragma unroll
            for (int it = 0; it < 4; it++) {
                int idx = it * 256 + tid;
                int row = idx >> 3, cq = (idx & 7) << 2;
                if (bm + row < M) ra[it] = *(const float4*)&A[(long)(bm + row) * K + kn + cq];
                else              ra[it] = make_float4(0.f, 0.f, 0.f, 0.f);
                int rowB = idx >> 5, cqB = (idx & 31) << 2;
                rb[it] = *(const float4*)&B[(long)(kn + rowB) * N + bn + cqB];
            }
        }

#pragma unroll
        for (int kk = 0; kk < 32; kk += 8) {
            uint32_t a[2][4];
#pragma unroll
            for (int mi = 0; mi < 2; mi++) {
                int r0 = wm + mi * 16 + gr;
                a[mi][0] = As[r0 * AS_LD + kk + tg];
                a[mi][1] = As[(r0 + 8) * AS_LD + kk + tg];
                a[mi][2] = As[r0 * AS_LD + kk + tg + 4];
                a[mi][3] = As[(r0 + 8) * AS_LD + kk + tg + 4];
            }
            uint32_t b[8][2];
#pragma unroll
            for (int ni = 0; ni < 8; ni++) {
                int col = wn + ni * 8 + gr;
                b[ni][0] = Bs[(kk + tg) * BS_LD + col];
                b[ni][1] = Bs[(kk + tg + 4) * BS_LD + col];
            }
#pragma unroll
            for (int mi = 0; mi < 2; mi++)
#pragma unroll
                for (int ni = 0; ni < 8; ni++) {
                    asm volatile(
                        "mma.sync.aligned.m16n8k8.row.col.f32.tf32.tf32.f32 "
                        "{%0,%1,%2,%3},{%4,%5,%6,%7},{%8,%9},{%0,%1,%2,%3};"
                        : "+f"(c[mi][ni][0]), "+f"(c[mi][ni][1]),
                          "+f"(c[mi][ni][2]), "+f"(c[mi][ni][3])
                        : "r"(a[mi][0]), "r"(a[mi][1]), "r"(a[mi][2]), "r"(a[mi][3]),
                          "r"(b[ni][0]), "r"(b[ni][1]));
                }
        }
        __syncthreads();
    }

    // epilogue: bias + optional relu
#pragma unroll
    for (int mi = 0; mi < 2; mi++) {
        int r0 = bm + wm + mi * 16 + gr;
        int r1 = r0 + 8;
#pragma unroll
        for (int ni = 0; ni < 8; ni++) {
            int col = bn + wn + ni * 8 + tg * 2;
            float b0 = bias[col], b1 = bias[col + 1];
            float v0 = c[mi][ni][0] + b0, v1 = c[mi][ni][1] + b1;
            float v2 = c[mi][ni][2] + b0, v3 = c[mi][ni][3] + b1;
            if (RELU) {
                v0 = fmaxf(v0, 0.f); v1 = fmaxf(v1, 0.f);
                v2 = fmaxf(v2, 0.f); v3 = fmaxf(v3, 0.f);
            }
            if (r0 < M) { float2 p = make_float2(v0, v1); *(float2*)&C[(long)r0 * N + col] = p; }
            if (r1 < M) { float2 p = make_float2(v2, v3); *(float2*)&C[(long)r1 * N + col] = p; }
        }
    }
}

// ---------------- BatchNorm ----------------
__global__ void k_bn_reduce() {
    int c = threadIdx.x;                         // 128 channels
    int rows_per = (N_NODES + gridDim.x - 1) / gridDim.x;
    int r0 = blockIdx.x * rows_per;
    int r1 = min(r0 + rows_per, N_NODES);
    float s = 0.f, s2 = 0.f;
    for (int r = r0; r < r1; r++) {
        float v = g_pre[(long)r * GHC + c];
        s += v; s2 += v * v;
    }
    atomicAdd(&g_sum[c], (double)s);
    atomicAdd(&g_sumsq[c], (double)s2);
}

__global__ void k_bn_final(const float* __restrict__ gamma, const float* __restrict__ beta) {
    int c = threadIdx.x;
    double mu = g_sum[c] / (double)N_NODES;
    double var = g_sumsq[c] / (double)N_NODES - mu * mu;
    double inv = 1.0 / sqrt(var + (double)BN_EPS);
    double sc = (double)gamma[c] * inv;
    g_scale[c] = (float)sc;
    g_shift[c] = (float)((double)beta[c] - mu * sc);
}

// BN apply + relu + store next-layer input + segmented mean pool (no atomics).
// Block = graph, thread = channel. batch is sorted -> contiguous row ranges.
__global__ void __launch_bounds__(GHC)
k_bn_pool(int lofs) {
    int g = blockIdx.x;
    int c = threadIdx.x;
    int r0 = g_gstart[g], r1 = g_gstart[g + 1];
    float sc = g_scale[c], sh = g_shift[c];
    float a0 = 0.f, a1 = 0.f;
    int r = r0;
    for (; r + 1 < r1; r += 2) {
        float v0 = g_pre[(long)r * GHC + c] * sc + sh;
        float v1 = g_pre[(long)(r + 1) * GHC + c] * sc + sh;
        v0 = fmaxf(v0, 0.f); v1 = fmaxf(v1, 0.f);
        g_h[(long)r * GHC + c] = v0;
        g_h[(long)(r + 1) * GHC + c] = v1;
        a0 += v0; a1 += v1;
    }
    if (r < r1) {
        float v = g_pre[(long)r * GHC + c] * sc + sh;
        v = fmaxf(v, 0.f);
        g_h[(long)r * GHC + c] = v;
        a0 += v;
    }
    int cnt = r1 - r0;
    float inv = (cnt > 0) ? (1.f / (float)cnt) : 0.f;
    g_z[(long)g * ZDIM + lofs + c] = (a0 + a1) * inv;
}

// ---------------- launch ----------------
extern "C" void kernel_launch(void* const* d_in, const int* in_sizes, int n_in,
                              void* d_out, int out_size) {
    const float* x      = (const float*)d_in[0];
    const void*  ei     = d_in[1];
    const void*  batch  = d_in[2];
    const float* W1_0   = (const float*)d_in[3];
    const float* b1_0   = (const float*)d_in[4];
    const float* W2_0   = (const float*)d_in[5];
    const float* b2_0   = (const float*)d_in[6];
    const float* W1s    = (const float*)d_in[7];
    const float* b1s    = (const float*)d_in[8];
    const float* W2s    = (const float*)d_in[9];
    const float* b2s    = (const float*)d_in[10];
    const float* gamma  = (const float*)d_in[11];
    const float* beta   = (const float*)d_in[12];
    const float* Wm1    = (const float*)d_in[13];
    const float* bm1    = (const float*)d_in[14];
    const float* Wm2    = (const float*)d_in[15];
    const float* bm2    = (const float*)d_in[16];
    float* out = (float*)d_out;

    void *p_hsum, *p_hid, *p_pre, *p_z, *p_zh, *p_deg, *p_sum;
    cudaGetSymbolAddress(&p_hsum, g_hsum);
    cudaGetSymbolAddress(&p_hid,  g_hid);
    cudaGetSymbolAddress(&p_pre,  g_pre);
    cudaGetSymbolAddress(&p_z,    g_z);
    cudaGetSymbolAddress(&p_zh,   g_zh);
    cudaGetSymbolAddress(&p_deg,  g_deg);
    cudaGetSymbolAddress(&p_sum,  g_sum);

    const int NB = (N_NODES + 1023) / 1024;   // 98

    // dtype probe + CSR build + graph segments
    k_probe<<<1, 32>>>((const unsigned int*)ei);
    k_zero_u32<<<(N_NODES + 255) / 256, 256>>>((unsigned int*)p_deg, N_NODES);
    k_deg<<<(N_EDGES + 255) / 256, 256>>>(ei);
    k_gstart<<<(N_GRAPHS + 1 + 127) / 128, 128>>>(batch);
    k_scan1<<<NB, 1024>>>();
    k_scan2<<<1, 1>>>(NB);
    k_scan3<<<NB, 1024>>>();
    k_scatter<<<(N_EDGES + 255) / 256, 256>>>(ei);

    dim3 gA((N_NODES * 32 + 255) / 256);      // warp per node

    const int MB = (N_NODES + 127) / 128;     // 782 blocks in M

    for (int l = 0; l < N_LAYERS; l++) {
        int K1;
        const float *W1, *B1, *W2, *B2;
        if (l == 0) {
            K1 = F_IN; W1 = W1_0; B1 = b1_0; W2 = W2_0; B2 = b2_0;
            k_agg32<<<gA, 256>>>(x);
        } else {
            K1 = GHC;
            W1 = W1s + (long)(l - 1) * GHC * 2 * GHC;
            B1 = b1s + (long)(l - 1) * 2 * GHC;
            W2 = W2s + (long)(l - 1) * 2 * GHC * GHC;
            B2 = b2s + (long)(l - 1) * GHC;
            k_agg128<<<gA, 256>>>();
        }
        // MLP (TF32 tensor cores)
        {
            dim3 g1(MB, (2 * GHC) / 128);
            k_mma<true><<<g1, 256>>>((const float*)p_hsum, W1, B1, (float*)p_hid,
                                     N_NODES, 2 * GHC, K1);
            dim3 g2(MB, GHC / 128);
            k_mma<false><<<g2, 256>>>((const float*)p_hid, W2, B2, (float*)p_pre,
                                      N_NODES, GHC, 2 * GHC);
        }
        // BN stats + fused apply/relu/pool (atomic-free pooling)
        k_zero_u32<<<1, 512>>>((unsigned int*)p_sum, 4 * GHC);
        k_bn_reduce<<<256, GHC>>>();
        k_bn_final<<<1, GHC>>>(gamma + l * GHC, beta + l * GHC);
        k_bn_pool<<<N_GRAPHS, GHC>>>(l * GHC);
    }

    // final MLP
    {
        dim3 g1((N_GRAPHS + 127) / 128, NHID / 128);
        k_mma<true><<<g1, 256>>>((const float*)p_z, Wm1, bm1, (float*)p_zh,
                                 N_GRAPHS, NHID, ZDIM);
        dim3 g2((N_GRAPHS + 127) / 128, NOUT / 128);
        k_mma<false><<<g2, 256>>>((const float*)p_zh, Wm2, bm2, out,
                                  N_GRAPHS, NOUT, NHID);
    }
}

// round 4
// speedup vs baseline: 2.4663x; 1.2558x over previous
#include <cuda_runtime.h>
#include <cuda_bf16.h>
#include <math.h>
#include <stdint.h>

#define N_NODES 100000
#define N_EDGES 600000
#define N_GRAPHS 1024
#define F_IN 32
#define GHC 128
#define NHID 512
#define NOUT 256
#define N_LAYERS 5
#define BN_EPS 1e-5f
#define ZDIM (N_LAYERS * GHC)   // 640

// weight scratch offsets (floats)
#define OFF_W1_0 0
#define OFF_W2_0 8192
#define OFF_W1S  40960
#define OFF_W2S  172032
#define OFF_WM1  303104
#define OFF_WM2  630784
#define W_TOTAL  761856

// ---------------- device scratch (no allocations allowed) ----------------
__device__ float  g_hsum[N_NODES * GHC];
__device__ float  g_hid [N_NODES * 2 * GHC];
__device__ float  g_pre [N_NODES * GHC];
__device__ float  g_h   [N_NODES * GHC];
__device__ float  g_wtf [W_TOTAL];           // tf32-rounded weights
__device__ int    g_rowptr[N_NODES + 1];
__device__ int    g_deg   [N_NODES];         // degree, then scatter cursor
__device__ int    g_csr   [N_EDGES];
__device__ int    g_blocktotals[128];
__device__ volatile int g_scanflag[128];
__device__ float  g_fsum[GHC], g_fsq[GHC];
__device__ float  g_scale[GHC], g_shift[GHC];
__device__ float  g_z  [N_GRAPHS * ZDIM];
__device__ float  g_zh [N_GRAPHS * NHID];
__device__ int    g_gstart[N_GRAPHS + 1];
__device__ int    g_is64;

// ---------------- helpers ----------------
__device__ __forceinline__ int ld_idx(const void* p, long i) {
    if (g_is64) return (int)((const long long*)p)[i];
    return ((const int*)p)[i];
}

__device__ __forceinline__ uint32_t f2tf(float f) {
    uint32_t u;
    asm("cvt.rna.tf32.f32 %0, %1;" : "=r"(u) : "f"(f));
    return u;
}
__device__ __forceinline__ float f2tf_f(float f) { return __uint_as_float(f2tf(f)); }

__device__ __forceinline__ void cp16(uint32_t saddr, const void* g, unsigned sz) {
    asm volatile("cp.async.cg.shared.global [%0], [%1], 16, %2;"
                 :: "r"(saddr), "l"(g), "r"(sz));
}
__device__ __forceinline__ void cpcommit() { asm volatile("cp.async.commit_group;"); }
template<int W> __device__ __forceinline__ void cpwait() {
    asm volatile("cp.async.wait_group %0;" :: "n"(W));
}

__global__ void k_probe(const unsigned int* ei_words) {
    if (threadIdx.x == 0 && blockIdx.x == 0) {
        unsigned int nz = 0;
        for (int i = 0; i < 256; i++) nz |= ei_words[2 * i + 1];
        g_is64 = (nz == 0) ? 1 : 0;
    }
}

// init: zero deg/flags, gstart binary search, convert all weights to tf32
__global__ void k_init(const void* batch,
                       const float* W1_0, const float* W2_0,
                       const float* W1s, const float* W2s,
                       const float* Wm1, const float* Wm2) {
    int i = blockIdx.x * blockDim.x + threadIdx.x;
    if (i < N_NODES) g_deg[i] = 0;
    if (i < 128) { g_scanflag[i] = 0; g_blocktotals[i] = 0; }
    if (i <= N_GRAPHS) {
        int g = i, lo = 0, hi = N_NODES;
        while (lo < hi) {
            int mid = (lo + hi) >> 1;
            if (ld_idx(batch, mid) < g) lo = mid + 1; else hi = mid;
        }
        g_gstart[i] = lo;
    }
    if (i < W_TOTAL) {
        float v;
        if      (i < OFF_W2_0) v = W1_0[i - OFF_W1_0];
        else if (i < OFF_W1S)  v = W2_0[i - OFF_W2_0];
        else if (i < OFF_W2S)  v = W1s[i - OFF_W1S];
        else if (i < OFF_WM1)  v = W2s[i - OFF_W2S];
        else if (i < OFF_WM2)  v = Wm1[i - OFF_WM1];
        else                   v = Wm2[i - OFF_WM2];
        g_wtf[i] = f2tf_f(v);
    }
}

__global__ void k_deg(const void* ei) {
    int e = blockIdx.x * blockDim.x + threadIdx.x;
    if (e < N_EDGES) {
        int dst = ld_idx(ei, (long)N_EDGES + e);
        atomicAdd(&g_deg[dst], 1);
    }
}

// single-kernel exclusive scan over g_deg (98 blocks, all resident in wave 1)
__global__ void k_scan() {
    __shared__ int sh[1024];
    __shared__ int s_off;
    int b = blockIdx.x, t = threadIdx.x;
    int gid = b * 1024 + t;
    int v = (gid < N_NODES) ? g_deg[gid] : 0;
    sh[t] = v;
    __syncthreads();
    for (int off = 1; off < 1024; off <<= 1) {
        int tmp = (t >= off) ? sh[t - off] : 0;
        __syncthreads();
        sh[t] += tmp;
        __syncthreads();
    }
    if (t == 1023) {
        g_blocktotals[b] = sh[1023];
        __threadfence();
        g_scanflag[b] = 1;
    }
    if (t == 0) s_off = 0;
    __syncthreads();
    if (t < b) {                       // decoupled lookback: read all predecessors
        while (g_scanflag[t] == 0) {}
        int tot = atomicAdd(&g_blocktotals[t], 0);   // forced L2 read after flag
        atomicAdd(&s_off, tot);
    }
    __syncthreads();
    int excl = sh[t] - v + s_off;
    if (gid < N_NODES) { g_rowptr[gid] = excl; g_deg[gid] = excl; }
    if (gid == 0) g_rowptr[N_NODES] = N_EDGES;
}

__global__ void k_scatter(const void* ei) {
    int e = blockIdx.x * blockDim.x + threadIdx.x;
    if (e < N_EDGES) {
        int src = ld_idx(ei, e);
        int dst = ld_idx(ei, (long)N_EDGES + e);
        int pos = atomicAdd(&g_deg[dst], 1);
        g_csr[pos] = src;
    }
}

// ---------------- aggregation (writes tf32-rounded, zeroes BN stats) -----
__global__ void k_agg32(const float* __restrict__ x) {
    int t = blockIdx.x * blockDim.x + threadIdx.x;
    if (t < 128) g_fsum[t] = 0.f;
    else if (t < 256) g_fsq[t - 128] = 0.f;
    int node = t >> 5, lane = t & 31;
    if (node >= N_NODES) return;
    float acc = x[node * 32 + lane];
    int e0 = g_rowptr[node], e1 = g_rowptr[node + 1];
    for (int e = e0; e < e1; e++) {
        int s = g_csr[e];
        acc += x[s * 32 + lane];
    }
    g_hsum[node * 32 + lane] = f2tf_f(acc);
}

__global__ void k_agg128() {
    int t = blockIdx.x * blockDim.x + threadIdx.x;
    if (t < 128) g_fsum[t] = 0.f;
    else if (t < 256) g_fsq[t - 128] = 0.f;
    int node = t >> 5, lane = t & 31;
    if (node >= N_NODES) return;
    const float4* hin = (const float4*)g_h;
    float4 acc = hin[node * 32 + lane];
    int e0 = g_rowptr[node], e1 = g_rowptr[node + 1];
    for (int e = e0; e < e1; e++) {
        int s = g_csr[e];
        float4 v = hin[s * 32 + lane];
        acc.x += v.x; acc.y += v.y; acc.z += v.z; acc.w += v.w;
    }
    float4 o;
    o.x = f2tf_f(acc.x); o.y = f2tf_f(acc.y);
    o.z = f2tf_f(acc.z); o.w = f2tf_f(acc.w);
    ((float4*)g_hsum)[node * 32 + lane] = o;
}

// ---------------- TF32 tensor-core GEMM, cp.async 2-stage pipeline -------
// All inputs PRE-ROUNDED to tf32-representable fp32. No cvt inside.
// Block tile 128x128x32, 256 threads, warp tile 32x64.
#define AS_LD 36
#define BS_LD 136
#define A_STG (128 * AS_LD)
#define B_STG (32 * BS_LD)
#define SMEM_BYTES ((2 * A_STG + 2 * B_STG) * 4)

template<bool RELU, bool ROUND, bool STATS>
__global__ void __launch_bounds__(256)
k_mma(const float* __restrict__ A, const float* __restrict__ B,
      const float* __restrict__ bias, float* __restrict__ C,
      int M, int N, int K) {
    extern __shared__ float dsm[];
    float* As = dsm;                 // [2][128][AS_LD]
    float* Bs = dsm + 2 * A_STG;     // [2][32][BS_LD]

    const int tid  = threadIdx.x;
    const int bm   = blockIdx.x * 128, bn = blockIdx.y * 128;
    const int warp = tid >> 5, lane = tid & 31;
    const int wm   = (warp & 3) * 32;
    const int wn   = (warp >> 2) * 64;
    const int gr   = lane >> 2, tg = lane & 3;

    const uint32_t sA = (uint32_t)__cvta_generic_to_shared(As);
    const uint32_t sB = (uint32_t)__cvta_generic_to_shared(Bs);

    float c[2][8][4];
#pragma unroll
    for (int mi = 0; mi < 2; mi++)
#pragma unroll
        for (int ni = 0; ni < 8; ni++)
#pragma unroll
            for (int j = 0; j < 4; j++) c[mi][ni][j] = 0.f;

    const int rowA = tid >> 1;                 // A loads: 2 chunks/row... see below
    // A tile 128x32 = 1024 x 16B chunks; B tile 32x128 = 1024 chunks; 4 each/thread
    auto load_stage = [&](int k0, int s) {
#pragma unroll
        for (int it = 0; it < 4; it++) {
            int idx = it * 256 + tid;
            int row = idx >> 3, cq = (idx & 7) << 2;
            long ar = bm + row;
            unsigned sz = (ar < M) ? 16u : 0u;
            long arc = (ar < M) ? ar : (M - 1);
            cp16(sA + (s * A_STG + row * AS_LD + cq) * 4,
                 A + arc * K + k0 + cq, sz);
            int rowB = idx >> 5, cqB = (idx & 31) << 2;
            cp16(sB + (s * B_STG + rowB * BS_LD + cqB) * 4,
                 B + (long)(k0 + rowB) * N + bn + cqB, 16u);
        }
        cpcommit();
    };
    (void)rowA;

    load_stage(0, 0);
    const int T = K >> 5;

    for (int i = 0; i < T; i++) {
        if (i + 1 < T) { load_stage((i + 1) << 5, (i + 1) & 1); cpwait<1>(); }
        else           { cpwait<0>(); }
        __syncthreads();

        const float* as = As + (i & 1) * A_STG;
        const float* bs = Bs + (i & 1) * B_STG;
#pragma unroll
        for (int kk = 0; kk < 32; kk += 8) {
            uint32_t a[2][4];
#pragma unroll
            for (int mi = 0; mi < 2; mi++) {
                int r0 = wm + mi * 16 + gr;
                a[mi][0] = __float_as_uint(as[r0 * AS_LD + kk + tg]);
                a[mi][1] = __float_as_uint(as[(r0 + 8) * AS_LD + kk + tg]);
                a[mi][2] = __float_as_uint(as[r0 * AS_LD + kk + tg + 4]);
                a[mi][3] = __float_as_uint(as[(r0 + 8) * AS_LD + kk + tg + 4]);
            }
            uint32_t b[8][2];
#pragma unroll
            for (int ni = 0; ni < 8; ni++) {
                int col = wn + ni * 8 + gr;
                b[ni][0] = __float_as_uint(bs[(kk + tg) * BS_LD + col]);
                b[ni][1] = __float_as_uint(bs[(kk + tg + 4) * BS_LD + col]);
            }
#pragma unroll
            for (int mi = 0; mi < 2; mi++)
#pragma unroll
                for (int ni = 0; ni < 8; ni++) {
                    asm volatile(
                        "mma.sync.aligned.m16n8k8.row.col.f32.tf32.tf32.f32 "
                        "{%0,%1,%2,%3},{%4,%5,%6,%7},{%8,%9},{%0,%1,%2,%3};"
                        : "+f"(c[mi][ni][0]), "+f"(c[mi][ni][1]),
                          "+f"(c[mi][ni][2]), "+f"(c[mi][ni][3])
                        : "r"(a[mi][0]), "r"(a[mi][1]), "r"(a[mi][2]), "r"(a[mi][3]),
                          "r"(b[ni][0]), "r"(b[ni][1]));
                }
        }
        __syncthreads();
    }

    // epilogue: bias (+relu) (+tf32 round) (+BN stats)
    float ssum[8][2], ssq[8][2];
    if (STATS) {
#pragma unroll
        for (int ni = 0; ni < 8; ni++) {
            ssum[ni][0] = ssum[ni][1] = 0.f;
            ssq[ni][0] = ssq[ni][1] = 0.f;
        }
    }
#pragma unroll
    for (int mi = 0; mi < 2; mi++) {
        int r0 = bm + wm + mi * 16 + gr;
        int r1 = r0 + 8;
#pragma unroll
        for (int ni = 0; ni < 8; ni++) {
            int col = bn + wn + ni * 8 + tg * 2;
            float b0 = bias[col], b1 = bias[col + 1];
            float v0 = c[mi][ni][0] + b0, v1 = c[mi][ni][1] + b1;
            float v2 = c[mi][ni][2] + b0, v3 = c[mi][ni][3] + b1;
            if (RELU) {
                v0 = fmaxf(v0, 0.f); v1 = fmaxf(v1, 0.f);
                v2 = fmaxf(v2, 0.f); v3 = fmaxf(v3, 0.f);
            }
            if (STATS) {
                if (r0 < M) { ssum[ni][0] += v0; ssq[ni][0] += v0 * v0;
                              ssum[ni][1] += v1; ssq[ni][1] += v1 * v1; }
                if (r1 < M) { ssum[ni][0] += v2; ssq[ni][0] += v2 * v2;
                              ssum[ni][1] += v3; ssq[ni][1] += v3 * v3; }
            }
            if (ROUND) {
                v0 = f2tf_f(v0); v1 = f2tf_f(v1);
                v2 = f2tf_f(v2); v3 = f2tf_f(v3);
            }
            if (r0 < M) { float2 p = make_float2(v0, v1); *(float2*)&C[(long)r0 * N + col] = p; }
            if (r1 < M) { float2 p = make_float2(v2, v3); *(float2*)&C[(long)r1 * N + col] = p; }
        }
    }
    if (STATS) {
#pragma unroll
        for (int ni = 0; ni < 8; ni++)
#pragma unroll
            for (int j = 0; j < 2; j++) {
#pragma unroll
                for (int m = 4; m <= 16; m <<= 1) {
                    ssum[ni][j] += __shfl_xor_sync(0xffffffffu, ssum[ni][j], m);
                    ssq[ni][j]  += __shfl_xor_sync(0xffffffffu, ssq[ni][j], m);
                }
            }
        if (gr == 0) {
#pragma unroll
            for (int ni = 0; ni < 8; ni++) {
                int col = bn + wn + ni * 8 + tg * 2;
                atomicAdd(&g_fsum[col],     ssum[ni][0]);
                atomicAdd(&g_fsum[col + 1], ssum[ni][1]);
                atomicAdd(&g_fsq[col],      ssq[ni][0]);
                atomicAdd(&g_fsq[col + 1],  ssq[ni][1]);
            }
        }
    }
}

// ---------------- BatchNorm finalize + fused apply/pool ------------------
__global__ void k_bn_final(const float* __restrict__ gamma, const float* __restrict__ beta) {
    int c = threadIdx.x;
    double mu = (double)g_fsum[c] / (double)N_NODES;
    double var = (double)g_fsq[c] / (double)N_NODES - mu * mu;
    double inv = 1.0 / sqrt(var + (double)BN_EPS);
    double sc = (double)gamma[c] * inv;
    g_scale[c] = (float)sc;
    g_shift[c] = (float)((double)beta[c] - mu * sc);
}

__global__ void __launch_bounds__(GHC)
k_bn_pool(int lofs) {
    int g = blockIdx.x;
    int c = threadIdx.x;
    int r0 = g_gstart[g], r1 = g_gstart[g + 1];
    float sc = g_scale[c], sh = g_shift[c];
    float a0 = 0.f, a1 = 0.f;
    int r = r0;
    for (; r + 1 < r1; r += 2) {
        float v0 = f2tf_f(fmaxf(g_pre[(long)r * GHC + c] * sc + sh, 0.f));
        float v1 = f2tf_f(fmaxf(g_pre[(long)(r + 1) * GHC + c] * sc + sh, 0.f));
        g_h[(long)r * GHC + c] = v0;
        g_h[(long)(r + 1) * GHC + c] = v1;
        a0 += v0; a1 += v1;
    }
    if (r < r1) {
        float v = f2tf_f(fmaxf(g_pre[(long)r * GHC + c] * sc + sh, 0.f));
        g_h[(long)r * GHC + c] = v;
        a0 += v;
    }
    int cnt = r1 - r0;
    float inv = (cnt > 0) ? (1.f / (float)cnt) : 0.f;
    g_z[(long)g * ZDIM + lofs + c] = f2tf_f((a0 + a1) * inv);
}

// ---------------- launch ----------------
extern "C" void kernel_launch(void* const* d_in, const int* in_sizes, int n_in,
                              void* d_out, int out_size) {
    const float* x      = (const float*)d_in[0];
    const void*  ei     = d_in[1];
    const void*  batch  = d_in[2];
    const float* W1_0   = (const float*)d_in[3];
    const float* b1_0   = (const float*)d_in[4];
    const float* W2_0   = (const float*)d_in[5];
    const float* b2_0   = (const float*)d_in[6];
    const float* W1s    = (const float*)d_in[7];
    const float* b1s    = (const float*)d_in[8];
    const float* W2s    = (const float*)d_in[9];
    const float* b2s    = (const float*)d_in[10];
    const float* gamma  = (const float*)d_in[11];
    const float* beta   = (const float*)d_in[12];
    /* Wm1 = d_in[13] */
    const float* bm1    = (const float*)d_in[14];
    /* Wm2 = d_in[15] */
    const float* bm2    = (const float*)d_in[16];
    float* out = (float*)d_out;

    void *p_hsum, *p_hid, *p_pre, *p_z, *p_zh, *p_wtf;
    cudaGetSymbolAddress(&p_hsum, g_hsum);
    cudaGetSymbolAddress(&p_hid,  g_hid);
    cudaGetSymbolAddress(&p_pre,  g_pre);
    cudaGetSymbolAddress(&p_z,    g_z);
    cudaGetSymbolAddress(&p_zh,   g_zh);
    cudaGetSymbolAddress(&p_wtf,  g_wtf);
    const float* wtf = (const float*)p_wtf;

    static bool attr_done = false;
    if (!attr_done) {
        cudaFuncSetAttribute(k_mma<true,  true,  false>, cudaFuncAttributeMaxDynamicSharedMemorySize, SMEM_BYTES);
        cudaFuncSetAttribute(k_mma<false, false, true >, cudaFuncAttributeMaxDynamicSharedMemorySize, SMEM_BYTES);
        cudaFuncSetAttribute(k_mma<false, false, false>, cudaFuncAttributeMaxDynamicSharedMemorySize, SMEM_BYTES);
        attr_done = true;
    }

    // setup: probe, init(zero+gstart+weight-cvt), deg, scan, scatter
    k_probe<<<1, 32>>>((const unsigned int*)ei);
    k_init<<<(W_TOTAL + 255) / 256, 256>>>(batch, W1_0, W2_0,
                                           (const float*)d_in[7], (const float*)d_in[9],
                                           (const float*)d_in[13], (const float*)d_in[15]);
    k_deg<<<(N_EDGES + 255) / 256, 256>>>(ei);
    k_scan<<<(N_NODES + 1023) / 1024, 1024>>>();
    k_scatter<<<(N_EDGES + 255) / 256, 256>>>(ei);

    dim3 gA((N_NODES * 32 + 255) / 256);
    const int MB = (N_NODES + 127) / 128;

    for (int l = 0; l < N_LAYERS; l++) {
        int K1;
        const float *W1, *B1, *W2, *B2;
        if (l == 0) {
            K1 = F_IN;
            W1 = wtf + OFF_W1_0; B1 = b1_0;
            W2 = wtf + OFF_W2_0; B2 = b2_0;
            k_agg32<<<gA, 256>>>(x);
        } else {
            K1 = GHC;
            W1 = wtf + OFF_W1S + (long)(l - 1) * GHC * 2 * GHC;
            B1 = b1s + (long)(l - 1) * 2 * GHC;
            W2 = wtf + OFF_W2S + (long)(l - 1) * 2 * GHC * GHC;
            B2 = b2s + (long)(l - 1) * GHC;
            k_agg128<<<gA, 256>>>();
        }
        dim3 g1(MB, (2 * GHC) / 128);
        k_mma<true, true, false><<<g1, 256, SMEM_BYTES>>>(
            (const float*)p_hsum, W1, B1, (float*)p_hid, N_NODES, 2 * GHC, K1);
        dim3 g2(MB, GHC / 128);
        k_mma<false, false, true><<<g2, 256, SMEM_BYTES>>>(
            (const float*)p_hid, W2, B2, (float*)p_pre, N_NODES, GHC, 2 * GHC);
        k_bn_final<<<1, GHC>>>(gamma + l * GHC, beta + l * GHC);
        k_bn_pool<<<N_GRAPHS, GHC>>>(l * GHC);
    }

    // final MLP
    {
        dim3 g1((N_GRAPHS + 127) / 128, NHID / 128);
        k_mma<true, true, false><<<g1, 256, SMEM_BYTES>>>(
            (const float*)p_z, wtf + OFF_WM1, bm1, (float*)p_zh, N_GRAPHS, NHID, ZDIM);
        dim3 g2((N_GRAPHS + 127) / 128, NOUT / 128);
        k_mma<false, false, false><<<g2, 256, SMEM_BYTES>>>(
            (const float*)p_zh, wtf + OFF_WM2, bm2, out, N_GRAPHS, NOUT, NHID);
    }
}